// round 14
// baseline (speedup 1.0000x reference)
#include <cuda_runtime.h>
#include <cuda_bf16.h>
#include <math.h>
#include <stdint.h>

// Problem dims (fixed by the dataset)
#define LT   512
#define DIN  512
#define NS   512
#define DOUT 512
#define BZ   32
#define MTOT (BZ*LT)

// ---------------- scratch (device globals; no allocation allowed) ------------
__device__ float          g_Bq [NS*DIN];
__device__ __nv_bfloat16  g_Dqb[DOUT*DIN];
__device__ __nv_bfloat16  g_Cqb[DOUT*NS];
__device__ float          g_Aq [NS];
__device__ float          g_X  [BZ*LT*NS];    // X[b,t,n] fp32 (bit-exact)
__device__ float          g_DU [BZ*DOUT*LT];  // DU[b,o,t]
__device__ __nv_bfloat16  g_Sb [BZ*LT*NS];    // S[b,t,n] bf16 (exact)

// ---------------- quantizer (proven bit-exact) --------------------------------
__device__ __forceinline__ float q8(float x) {
    float xa = fabsf(x);
    float z  = xa + 1e-8f;
    int   e  = (__float_as_int(z) >> 23) - 127;
    e = max(-7, min(7, e));
    float p    = __int_as_float((e + 127) << 23);
    float pinv = __int_as_float((127 - e) << 23);
    float mant = rintf(fmaf(xa, pinv, -1.0f) * 8.0f) * 0.125f;
    float r = (1.0f + mant) * p;
    return copysignf(r, x);
}

// ---------------- weight quantization ----------------------------------------
__global__ void quant_weights(const float* __restrict__ A, const float* __restrict__ B,
                              const float* __restrict__ C, const float* __restrict__ D) {
    int i = blockIdx.x * blockDim.x + threadIdx.x;
    if (i < NS*DIN) {
        g_Bq [i] = q8(B[i]);
        g_Dqb[i] = __float2bfloat16(q8(D[i]));
        g_Cqb[i] = __float2bfloat16(q8(C[i]));
    }
    if (i < NS) g_Aq[i] = q8(A[i]);
}

// ---------------- smem structs -------------------------------------------------
struct XSmem { float As[2][8][128]; float Ws[2][8][128]; };                 // 16384 B
struct DSmem { __nv_bfloat16 A[128][40]; __nv_bfloat16 Bk[32][72]; };      // 14848 B
struct YSmem { __nv_bfloat16 A[2][128][40]; __nv_bfloat16 B[2][64][40]; }; // 30720 B

__device__ __forceinline__ uint32_t smem_u32p(const void* p) {
    return (uint32_t)__cvta_generic_to_shared(p);
}
__device__ __forceinline__ void ldsm4(uint32_t r[4], uint32_t addr) {
    asm volatile("ldmatrix.sync.aligned.m8n8.x4.shared.b16 {%0,%1,%2,%3}, [%4];"
                 : "=r"(r[0]), "=r"(r[1]), "=r"(r[2]), "=r"(r[3]) : "r"(addr));
}
__device__ __forceinline__ void ldsm4t(uint32_t r[4], uint32_t addr) {
    asm volatile("ldmatrix.sync.aligned.m8n8.x4.trans.shared.b16 {%0,%1,%2,%3}, [%4];"
                 : "=r"(r[0]), "=r"(r[1]), "=r"(r[2]), "=r"(r[3]) : "r"(addr));
}
__device__ __forceinline__ void mma16816(float c[4], const uint32_t a[4], uint32_t b0, uint32_t b1) {
    asm volatile(
        "mma.sync.aligned.m16n8k16.row.col.f32.bf16.bf16.f32 "
        "{%0,%1,%2,%3}, {%4,%5,%6,%7}, {%8,%9}, {%0,%1,%2,%3};"
        : "+f"(c[0]), "+f"(c[1]), "+f"(c[2]), "+f"(c[3])
        : "r"(a[0]), "r"(a[1]), "r"(a[2]), "r"(a[3]), "r"(b0), "r"(b1));
}

// packed dual-fp32 fma (bit-exact lanes)
__device__ __forceinline__ void fma2(unsigned long long& c,
                                     unsigned long long a, unsigned long long b) {
    asm("fma.rn.f32x2 %0, %1, %2, %0;" : "+l"(c) : "l"(a), "l"(b));
}
__device__ __forceinline__ unsigned long long dup2(float x) {
    unsigned long long r; uint32_t u = __float_as_uint(x);
    asm("mov.b64 %0, {%1, %1};" : "=l"(r) : "r"(u));
    return r;
}
__device__ __forceinline__ uint32_t packbf2(__nv_bfloat16 lo, __nv_bfloat16 hi) {
    return (uint32_t)__bfloat16_as_ushort(lo) | ((uint32_t)__bfloat16_as_ushort(hi) << 16);
}

// ---------------- gemm_x body: exact fp32 (bit-exact ascending-k chain) --------
__device__ void gemm_x_body(const float* __restrict__ u, int bx, int by, XSmem& S) {
    constexpr int BK = 8;
    constexpr int NK = 512 / BK;

    const int tid = threadIdx.x;
    const int m0  = bx * 128;
    const int n0  = by * 128;
    const int b   = m0 >> 9;
    const int t0  = m0 & 511;

    const int wn = tid >> 1;
    const int wk = (tid & 1) * 4;
    const float* wptr = g_Bq + (n0 + wn) * 512 + wk;

    const int a_kl = tid >> 5;
    const int a_tl = (tid & 31) << 2;
    const float* aptr = u + b * (DIN * LT) + a_kl * LT + t0 + a_tl;

    const int tn = tid & 15, tm = tid >> 4;

    unsigned long long acc2[8][4];
#pragma unroll
    for (int i = 0; i < 8; i++)
#pragma unroll
        for (int jj = 0; jj < 4; jj++) acc2[i][jj] = 0ULL;

    {
        float4 w4 = *(const float4*)(wptr);
        S.Ws[0][wk+0][wn] = w4.x; S.Ws[0][wk+1][wn] = w4.y;
        S.Ws[0][wk+2][wn] = w4.z; S.Ws[0][wk+3][wn] = w4.w;
        *(float4*)&S.As[0][a_kl][a_tl] = *(const float4*)(aptr);
    }
    __syncthreads();

    for (int kt = 0; kt < NK; kt++) {
        const int buf = kt & 1;
        const bool more = (kt + 1 < NK);
        float4 na, nw;
        if (more) {
            const int k0 = (kt + 1) * BK;
            nw = *(const float4*)(wptr + k0);
            na = *(const float4*)(aptr + k0 * LT);
        }
#pragma unroll
        for (int kk = 0; kk < BK; kk++) {
            unsigned long long rad[8];
#pragma unroll
            for (int i = 0; i < 8; i++)
                rad[i] = dup2(S.As[buf][kk][tm + 16*i]);
            unsigned long long rw2[4];
#pragma unroll
            for (int jj = 0; jj < 4; jj++)
                rw2[jj] = *(const unsigned long long*)&S.Ws[buf][kk][2*tn + 32*jj];
#pragma unroll
            for (int i = 0; i < 8; i++)
#pragma unroll
                for (int jj = 0; jj < 4; jj++)
                    fma2(acc2[i][jj], rad[i], rw2[jj]);
        }
        if (more) {
            const int nb = buf ^ 1;
            S.Ws[nb][wk+0][wn] = nw.x; S.Ws[nb][wk+1][wn] = nw.y;
            S.Ws[nb][wk+2][wn] = nw.z; S.Ws[nb][wk+3][wn] = nw.w;
            *(float4*)&S.As[nb][a_kl][a_tl] = na;
        }
        __syncthreads();
    }

#pragma unroll
    for (int i = 0; i < 8; i++) {
        const int m = m0 + tm + 16*i;
#pragma unroll
        for (int jj = 0; jj < 4; jj++) {
            float2 r;
            asm("mov.b64 {%0, %1}, %2;" : "=f"(r.x), "=f"(r.y) : "l"(acc2[i][jj]));
            *(float2*)&g_X[m * 512 + n0 + 2*tn + 32*jj] = r;
        }
    }
}

// ---------------- DU body: tensor GEMM with inline u->bf16 hi/lo convert -------
// DU[b][o][t] = sum_d Dq[o][d]*uhi[t][d]  (chunks 0-15)  + ... *ulo (16-31)
// Tile: o 128 x t 64. B operand built k-major in smem, fragments via ldsm.trans.
// Per-element fma-chain order identical to R10 -> DU bit-identical.
__device__ void du_body(const float* __restrict__ u, int bxt, int byo, int b, DSmem& S) {
    const int tid  = threadIdx.x;
    const int wid  = tid >> 5, lane = tid & 31;
    const int g    = lane >> 2, tq = lane & 3;
    const int wm   = wid >> 2;           // o: 2 x 64
    const int wn   = wid & 3;            // t: 4 x 16
    const int t0   = bxt * 64;
    const int o0   = byo * 128;

    // loader maps
    const int ar = tid >> 1, ac = (tid & 1) * 16;           // A: Dqb 128 x 32
    const int br = tid >> 3, bt = (tid & 7) * 8;            // B: u 32(d) x 64(t)
    const float* ubase = u + (size_t)b * (DIN * LT) + (size_t)br * LT + t0 + bt;
    const __nv_bfloat16* abase = g_Dqb + (size_t)(o0 + ar) * 512 + ac;

    const uint32_t smA = smem_u32p(&S.A[0][0]);
    const uint32_t smB = smem_u32p(&S.Bk[0][0]);
    // fragment addresses
    const uint32_t afA = smA + (wm * 64 + (lane & 15)) * 80 + (lane >> 4) * 16;
    const uint32_t bfB = smB + (((lane >> 3) & 1) * 8 + (lane & 7)) * 144
                             + (wn * 16 + ((lane >> 4) & 1) * 8) * 2;

    float acc[4][2][4];
#pragma unroll
    for (int i = 0; i < 4; i++)
#pragma unroll
        for (int j = 0; j < 2; j++)
#pragma unroll
            for (int r = 0; r < 4; r++) acc[i][j][r] = 0.0f;

    float4 f0, f1; uint4 ra0, ra1;
    auto ldg = [&](int c) {
        const int d0 = (c & 15) * 32;
        const float* up = ubase + (size_t)d0 * LT;
        f0 = *(const float4*)up;  f1 = *(const float4*)(up + 4);
        const uint4* ap = (const uint4*)(abase + d0);
        ra0 = ap[0]; ra1 = ap[1];
    };

    ldg(0);
    for (int c = 0; c < 32; c++) {
        __syncthreads();                 // prev chunk's ldsm reads done
        // STS A
        *(uint4*)&S.A[ar][ac]     = ra0;
        *(uint4*)&S.A[ar][ac + 8] = ra1;
        // convert + STS B (k-major row br, cols bt..bt+7)
        {
            float v[8] = {f0.x, f0.y, f0.z, f0.w, f1.x, f1.y, f1.z, f1.w};
            uint32_t pk[4];
            if (c < 16) {
#pragma unroll
                for (int e = 0; e < 4; e++)
                    pk[e] = packbf2(__float2bfloat16(v[2*e]), __float2bfloat16(v[2*e+1]));
            } else {
#pragma unroll
                for (int e = 0; e < 4; e++) {
                    __nv_bfloat16 h0 = __float2bfloat16(v[2*e]);
                    __nv_bfloat16 h1 = __float2bfloat16(v[2*e+1]);
                    pk[e] = packbf2(__float2bfloat16(v[2*e]   - __bfloat162float(h0)),
                                    __float2bfloat16(v[2*e+1] - __bfloat162float(h1)));
                }
            }
            *(uint4*)&S.Bk[br][bt] = *(uint4*)pk;
        }
        __syncthreads();                 // smem ready
        if (c + 1 < 32) ldg(c + 1);      // overlap with MMA

#pragma unroll
        for (int s = 0; s < 2; s++) {
            uint32_t af[4][4];
#pragma unroll
            for (int i = 0; i < 4; i++)
                ldsm4(af[i], afA + i * (16 * 80) + s * 32);
            uint32_t bq[4];
            ldsm4t(bq, bfB + s * 16 * 144);
#pragma unroll
            for (int i = 0; i < 4; i++)
#pragma unroll
                for (int j = 0; j < 2; j++)
                    mma16816(acc[i][j], af[i], bq[j * 2], bq[j * 2 + 1]);
        }
    }

#pragma unroll
    for (int i = 0; i < 4; i++) {
#pragma unroll
        for (int j = 0; j < 2; j++) {
            const int o = o0 + wm * 64 + i * 16 + g;
            const int t = t0 + wn * 16 + j * 8 + 2 * tq;
            const size_t rb = ((size_t)(b * 512 + o)) * 512 + t;
            *(float2*)&g_DU[rb]           = make_float2(acc[i][j][0], acc[i][j][1]);
            *(float2*)&g_DU[rb + 8 * 512] = make_float2(acc[i][j][2], acc[i][j][3]);
        }
    }
}

// ---------------- k2: gemm_x (bid%3==0) || DU inline-convert (else) ------------
__global__ __launch_bounds__(256, 2)
void k2(const float* __restrict__ u) {
    __shared__ __align__(16) char sm[sizeof(XSmem)];   // >= sizeof(DSmem)
    const int bid = blockIdx.x;
    if (bid % 3 == 0) {
        const int gid = bid / 3;                        // 0..511
        gemm_x_body(u, gid & 127, gid >> 7, *reinterpret_cast<XSmem*>(sm));
    } else {
        const int duid = bid - 1 - bid / 3;             // 0..1023
        du_body(u, duid & 7, (duid >> 3) & 3, duid >> 5,
                *reinterpret_cast<DSmem*>(sm));
    }
}

// ---------------- scan (unchanged arithmetic), standalone ----------------------
__global__ void scan_kernel() {
    const int id = blockIdx.x * blockDim.x + threadIdx.x;   // 0..16383
    const int n  = id & 511;
    const int bb = id >> 9;
    const float a = g_Aq[n];
    const float* __restrict__ xp = g_X + (size_t)(bb * 512) * 512 + n;
    __nv_bfloat16* __restrict__ sp = g_Sb + (size_t)(bb * 512) * 512 + n;

    float s = 0.0f;
    float buf[8];
#pragma unroll
    for (int k = 0; k < 8; k++) buf[k] = xp[k * 512];

    for (int blk = 0; blk < 64; blk++) {
        float nbuf[8];
        if (blk < 63) {
#pragma unroll
            for (int k = 0; k < 8; k++) nbuf[k] = xp[((blk + 1) * 8 + k) * 512];
        } else {
#pragma unroll
            for (int k = 0; k < 8; k++) nbuf[k] = 0.0f;
        }
#pragma unroll
        for (int k = 0; k < 8; k++) {
            s = q8(__fadd_rn(__fmul_rn(s, a), buf[k]));
            sp[(blk * 8 + k) * 512] = __float2bfloat16(s);
        }
#pragma unroll
        for (int k = 0; k < 8; k++) buf[k] = nbuf[k];
    }
}

// ---------------- tc_y: Y = q8(S @ Cq^T + DU), tiles 128(o) x 64(t) ------------
__global__ __launch_bounds__(256)
void tcy(float* __restrict__ Y) {
    __shared__ __align__(16) YSmem S;
    constexpr int NC = 16;

    const int tid  = threadIdx.x;
    const int wid  = tid >> 5, lane = tid & 31;
    const int g    = lane >> 2, tq = lane & 3;
    const int wm   = wid >> 2;           // o: 2 x 64
    const int wn   = wid & 3;            // t: 4 x 16
    const int t0   = blockIdx.x * 64;
    const int o0   = blockIdx.y * 128;
    const int b    = blockIdx.z;

    // loaders
    const int ar = tid >> 1, ac = (tid & 1) * 16;   // A: Cqb 128 x 32
    const int brr = tid >> 2, bq8 = (tid & 3) * 8;  // B: Sb 64 x 32
    const __nv_bfloat16* Ap = g_Cqb + (size_t)(o0 + ar) * 512 + ac;
    const __nv_bfloat16* Bp = g_Sb + ((size_t)b << 18) + (size_t)(t0 + brr) * 512 + bq8;

    uint4 ra0, ra1, rb0;
    auto ldg = [&](int c) {
        const uint4* pa = (const uint4*)(Ap + c * 32);
        ra0 = pa[0]; ra1 = pa[1];
        rb0 = *(const uint4*)(Bp + c * 32);
    };
    auto sts = [&](int bi) {
        *(uint4*)&S.A[bi][ar][ac]     = ra0;
        *(uint4*)&S.A[bi][ar][ac + 8] = ra1;
        *(uint4*)&S.B[bi][brr][bq8]   = rb0;
    };

    const uint32_t afA = smem_u32p(&S.A[0][0][0]) + (wm * 64 + (lane & 15)) * 80 + (lane >> 4) * 16;
    const uint32_t bfB = smem_u32p(&S.B[0][0][0])
                       + (wn * 16 + ((lane >> 4) & 1) * 8 + (lane & 7)) * 80
                       + ((lane >> 3) & 1) * 16;
    constexpr uint32_t ABUF = 128 * 40 * 2;
    constexpr uint32_t BBUF = 64 * 40 * 2;

    float acc[4][2][4];
#pragma unroll
    for (int i = 0; i < 4; i++)
#pragma unroll
        for (int j = 0; j < 2; j++)
#pragma unroll
            for (int r = 0; r < 4; r++) acc[i][j][r] = 0.0f;

    ldg(0); sts(0); __syncthreads();

    for (int c = 0; c < NC; c++) {
        const int bi = c & 1;
        const bool more = (c + 1 < NC);
        if (more) ldg(c + 1);

#pragma unroll
        for (int s = 0; s < 2; s++) {
            uint32_t af[4][4];
#pragma unroll
            for (int i = 0; i < 4; i++)
                ldsm4(af[i], afA + bi * ABUF + i * (16 * 80) + s * 32);
            uint32_t bq[4];
            ldsm4(bq, bfB + bi * BBUF + s * 32);
#pragma unroll
            for (int i = 0; i < 4; i++)
#pragma unroll
                for (int j = 0; j < 2; j++)
                    mma16816(acc[i][j], af[i], bq[j * 2], bq[j * 2 + 1]);
        }

        if (more) sts(bi ^ 1);
        __syncthreads();
    }

#pragma unroll
    for (int i = 0; i < 4; i++) {
#pragma unroll
        for (int j = 0; j < 2; j++) {
            const int o = o0 + wm * 64 + i * 16 + g;
            const int t = t0 + wn * 16 + j * 8 + 2 * tq;
            const size_t rb = ((size_t)(b * 512 + o)) * 512 + t;
            float2 d0 = *(const float2*)&g_DU[rb];
            float2 d1 = *(const float2*)&g_DU[rb + 8 * 512];
            *(float2*)&Y[rb] =
                make_float2(q8(acc[i][j][0] + d0.x), q8(acc[i][j][1] + d0.y));
            *(float2*)&Y[rb + 8 * 512] =
                make_float2(q8(acc[i][j][2] + d1.x), q8(acc[i][j][3] + d1.y));
        }
    }
}

// ---------------- launch --------------------------------------------------------
extern "C" void kernel_launch(void* const* d_in, const int* in_sizes, int n_in,
                              void* d_out, int out_size) {
    const float* u = (const float*)d_in[0];   // (32, 512, 512)  u[b,d,t]
    const float* A = (const float*)d_in[1];
    const float* B = (const float*)d_in[2];
    const float* C = (const float*)d_in[3];
    const float* D = (const float*)d_in[4];
    float* Y = (float*)d_out;                 // (32, 512, 512)  Y[b,o,t]

    quant_weights<<<1024, 256>>>(A, B, C, D);
    k2<<<1536, 256>>>(u);                     // gemm_x (bit-exact X) || DU (inline cvt)
    scan_kernel<<<128, 128>>>();              // S (bf16-exact) from X
    tcy<<<dim3(8, 4, BZ), 256>>>(Y);          // Y = q8(S @ Cq^T + DU)
}

// round 17
// speedup vs baseline: 1.2451x; 1.2451x over previous
#include <cuda_runtime.h>
#include <cuda_bf16.h>
#include <math.h>
#include <stdint.h>

// Problem dims (fixed by the dataset)
#define LT   512
#define DIN  512
#define NS   512
#define DOUT 512
#define BZ   32
#define MTOT (BZ*LT)

// ---------------- scratch (device globals; no allocation allowed) ------------
__device__ float          g_Bq [NS*DIN];
__device__ __nv_bfloat16  g_Dqb[DOUT*DIN];
__device__ __nv_bfloat16  g_Cqb[DOUT*NS];
__device__ float          g_Aq [NS];
__device__ float          g_X  [BZ*LT*NS];    // X[b,t,n] fp32 (bit-exact)
__device__ float          g_DU [BZ*DOUT*LT];  // DU[b,o,t]
__device__ __nv_bfloat16  g_Sb [BZ*LT*NS];    // S[b,t,n] bf16 (exact)
__device__ __nv_bfloat16  g_uhiT[BZ*LT*DIN];  // u^T hi [b,t,d]
__device__ __nv_bfloat16  g_uloT[BZ*LT*DIN];  // u^T lo [b,t,d]

// ---------------- quantizers ---------------------------------------------------
// reference formula (used only as the xa>=256 fallback; never taken in practice)
__device__ __forceinline__ float q8_ref(float x) {
    float xa = fabsf(x);
    float z  = xa + 1e-8f;
    int   e  = (__float_as_int(z) >> 23) - 127;
    e = max(-7, min(7, e));
    float p    = __int_as_float((e + 127) << 23);
    float pinv = __int_as_float((127 - e) << 23);
    float mant = rintf(fmaf(xa, pinv, -1.0f) * 8.0f) * 0.125f;
    float r = (1.0f + mant) * p;
    return copysignf(r, x);
}
// fast quantizer: RNE of the fp32 mantissa at 3 bits (== reference for
// 2^-7 <= |x| < 256, proven incl. ties/carries/the +1e-8 boundary sliver);
// |x| < 2^-7 -> rint(xa*1024)/1024 (== reference modulo ~1e-10-prob tie slivers).
__device__ __forceinline__ float q8f(float x) {
    uint32_t b = __float_as_uint(x) & 0x7FFFFFFFu;
    if (b >= 0x43800000u) return q8_ref(x);            // |x| >= 256: exact fallback
    float xa = __uint_as_float(b);
    uint32_t rbm = (b + ((b >> 20) & 1u) + 0x0007FFFFu) & 0xFFF00000u;
    float r_small = rintf(xa * 1024.0f) * 0.0009765625f;
    float r = (b < 0x3C000000u) ? r_small : __uint_as_float(rbm);
    return copysignf(r, x);
}

// ---------------- weight quantization ------------------------------------------
__global__ void quant_weights(const float* __restrict__ A, const float* __restrict__ B,
                              const float* __restrict__ C, const float* __restrict__ D) {
    int i = blockIdx.x * blockDim.x + threadIdx.x;
    if (i < NS*DIN) {
        g_Bq [i] = q8f(B[i]);
        g_Dqb[i] = __float2bfloat16(q8f(D[i]));
        g_Cqb[i] = __float2bfloat16(q8f(C[i]));
    }
    if (i < NS) g_Aq[i] = q8f(A[i]);
}

// ---------------- smem structs -------------------------------------------------
struct XSmem  { float As[2][8][128]; float Ws[2][8][128]; };
struct CSmem  { float tile[32][33]; };
struct TcSmem { __nv_bfloat16 A[2][128][40]; __nv_bfloat16 B[2][128][40]; };
#define TC_BUF_BYTES (128*40*2)

__device__ __forceinline__ uint32_t smem_u32p(const void* p) {
    return (uint32_t)__cvta_generic_to_shared(p);
}
__device__ __forceinline__ void ldsm4(uint32_t r[4], uint32_t addr) {
    asm volatile("ldmatrix.sync.aligned.m8n8.x4.shared.b16 {%0,%1,%2,%3}, [%4];"
                 : "=r"(r[0]), "=r"(r[1]), "=r"(r[2]), "=r"(r[3]) : "r"(addr));
}
__device__ __forceinline__ void mma16816(float c[4], const uint32_t a[4], uint32_t b0, uint32_t b1) {
    asm volatile(
        "mma.sync.aligned.m16n8k16.row.col.f32.bf16.bf16.f32 "
        "{%0,%1,%2,%3}, {%4,%5,%6,%7}, {%8,%9}, {%0,%1,%2,%3};"
        : "+f"(c[0]), "+f"(c[1]), "+f"(c[2]), "+f"(c[3])
        : "r"(a[0]), "r"(a[1]), "r"(a[2]), "r"(a[3]), "r"(b0), "r"(b1));
}

// packed dual-fp32 fma (bit-exact lanes)
__device__ __forceinline__ void fma2(unsigned long long& c,
                                     unsigned long long a, unsigned long long b) {
    asm("fma.rn.f32x2 %0, %1, %2, %0;" : "+l"(c) : "l"(a), "l"(b));
}
__device__ __forceinline__ unsigned long long dup2(float x) {
    unsigned long long r; uint32_t u = __float_as_uint(x);
    asm("mov.b64 %0, {%1, %1};" : "=l"(r) : "r"(u));
    return r;
}

// ---------------- gemm_x body: exact fp32 (bit-exact ascending-k chain) --------
__device__ void gemm_x_body(const float* __restrict__ u, int bx, int by, XSmem& S) {
    constexpr int BK = 8;
    constexpr int NK = 512 / BK;

    const int tid = threadIdx.x;
    const int m0  = bx * 128;
    const int n0  = by * 128;
    const int b   = m0 >> 9;
    const int t0  = m0 & 511;

    const int wn = tid >> 1;
    const int wk = (tid & 1) * 4;
    const float* wptr = g_Bq + (n0 + wn) * 512 + wk;

    const int a_kl = tid >> 5;
    const int a_tl = (tid & 31) << 2;
    const float* aptr = u + b * (DIN * LT) + a_kl * LT + t0 + a_tl;

    const int tn = tid & 15, tm = tid >> 4;

    unsigned long long acc2[8][4];
#pragma unroll
    for (int i = 0; i < 8; i++)
#pragma unroll
        for (int jj = 0; jj < 4; jj++) acc2[i][jj] = 0ULL;

    {
        float4 w4 = *(const float4*)(wptr);
        S.Ws[0][wk+0][wn] = w4.x; S.Ws[0][wk+1][wn] = w4.y;
        S.Ws[0][wk+2][wn] = w4.z; S.Ws[0][wk+3][wn] = w4.w;
        *(float4*)&S.As[0][a_kl][a_tl] = *(const float4*)(aptr);
    }
    __syncthreads();

    for (int kt = 0; kt < NK; kt++) {
        const int buf = kt & 1;
        const bool more = (kt + 1 < NK);
        float4 na, nw;
        if (more) {
            const int k0 = (kt + 1) * BK;
            nw = *(const float4*)(wptr + k0);
            na = *(const float4*)(aptr + k0 * LT);
        }
#pragma unroll
        for (int kk = 0; kk < BK; kk++) {
            unsigned long long rad[8];
#pragma unroll
            for (int i = 0; i < 8; i++)
                rad[i] = dup2(S.As[buf][kk][tm + 16*i]);
            unsigned long long rw2[4];
#pragma unroll
            for (int jj = 0; jj < 4; jj++)
                rw2[jj] = *(const unsigned long long*)&S.Ws[buf][kk][2*tn + 32*jj];
#pragma unroll
            for (int i = 0; i < 8; i++)
#pragma unroll
                for (int jj = 0; jj < 4; jj++)
                    fma2(acc2[i][jj], rad[i], rw2[jj]);
        }
        if (more) {
            const int nb = buf ^ 1;
            S.Ws[nb][wk+0][wn] = nw.x; S.Ws[nb][wk+1][wn] = nw.y;
            S.Ws[nb][wk+2][wn] = nw.z; S.Ws[nb][wk+3][wn] = nw.w;
            *(float4*)&S.As[nb][a_kl][a_tl] = na;
        }
        __syncthreads();
    }

#pragma unroll
    for (int i = 0; i < 8; i++) {
        const int m = m0 + tm + 16*i;
#pragma unroll
        for (int jj = 0; jj < 4; jj++) {
            float2 r;
            asm("mov.b64 {%0, %1}, %2;" : "=f"(r.x), "=f"(r.y) : "l"(acc2[i][jj]));
            *(float2*)&g_X[m * 512 + n0 + 2*tn + 32*jj] = r;
        }
    }
}

// ---------------- convert body: one 32x32 transpose tile -----------------------
__device__ void convert_body(const float* __restrict__ u, int gid, CSmem& S) {
    const int x = gid & 15, y = (gid >> 4) & 15, z = gid >> 8;
    const int d0 = y * 32, t0 = x * 32;
    const int tx = threadIdx.x & 31;
    const int ty = threadIdx.x >> 5;
    const size_t ub = (size_t)z * (DIN * LT);
#pragma unroll
    for (int p = 0; p < 4; p++)
        S.tile[ty + 8*p][tx] = u[ub + (size_t)(d0 + ty + 8*p) * LT + t0 + tx];
    __syncthreads();
#pragma unroll
    for (int p = 0; p < 4; p++) {
        float v = S.tile[tx][ty + 8*p];
        __nv_bfloat16 hi = __float2bfloat16(v);
        float r = v - __bfloat162float(hi);
        __nv_bfloat16 lo = __float2bfloat16(r);
        size_t idx = ub + (size_t)(t0 + ty + 8*p) * DIN + d0 + tx;
        g_uhiT[idx] = hi;
        g_uloT[idx] = lo;
    }
    __syncthreads();
}

// ---------------- fused1: gemm_x (even blocks) + convert (odd blocks) ---------
__global__ __launch_bounds__(256, 2)
void fused1(const float* __restrict__ u) {
    __shared__ __align__(16) char sm[sizeof(XSmem)];
    const int role = blockIdx.x & 1;
    const int id   = blockIdx.x >> 1;
    if (role == 0) {
        gemm_x_body(u, id & 127, id >> 7, *reinterpret_cast<XSmem*>(sm));
    } else {
        CSmem& S = *reinterpret_cast<CSmem*>(sm);
        for (int l = 0; l < 16; l++)
            convert_body(u, id * 16 + l, S);
    }
}

// ---------------- tc body (R10-exact): bf16 mma, dbl-buffered LDG->STS ---------
template <bool IS_Y>
__device__ void tc_body(float* __restrict__ Yout, int bxt, int byo, int b, TcSmem& S) {
    constexpr int NC = IS_Y ? 16 : 32;

    const int tid  = threadIdx.x;
    const int wid  = tid >> 5, lane = tid & 31;
    const int g    = lane >> 2, tq = lane & 3;
    const int wm   = wid >> 2;
    const int wn   = wid & 3;
    const int t0   = bxt * 128;
    const int o0   = byo * 128;

    const __nv_bfloat16* __restrict__ Ab  = IS_Y ? g_Cqb : g_Dqb;
    const __nv_bfloat16* __restrict__ Bhi = IS_Y ? g_Sb  : g_uhiT;
    const __nv_bfloat16* __restrict__ Blo = g_uloT;

    const int lrow = tid >> 1;
    const int lcol = (tid & 1) << 4;
    const __nv_bfloat16* Ap = Ab + (size_t)(o0 + lrow) * 512 + lcol;
    const size_t boff = ((size_t)b << 18) + (size_t)(t0 + lrow) * 512 + lcol;

    uint4 ra0, ra1, rb0, rb1;
    auto ldg = [&](int c) {
        const uint4* pa = (const uint4*)(Ap + (c & 15) * 32);
        ra0 = pa[0]; ra1 = pa[1];
        const __nv_bfloat16* src = (!IS_Y && c >= 16) ? Blo : Bhi;
        const uint4* pb = (const uint4*)(src + boff + (size_t)(c & 15) * 32);
        rb0 = pb[0]; rb1 = pb[1];
    };
    auto sts = [&](int bi) {
        *(uint4*)&S.A[bi][lrow][lcol]     = ra0;
        *(uint4*)&S.A[bi][lrow][lcol + 8] = ra1;
        *(uint4*)&S.B[bi][lrow][lcol]     = rb0;
        *(uint4*)&S.B[bi][lrow][lcol + 8] = rb1;
    };

    const int arow = wm * 64 + (lane & 15);
    const int acol = (lane >> 4) * 8;
    uint32_t aAddr0 = smem_u32p(&S.A[0][arow][acol]);
    const int brow = wn * 32 + ((lane >> 4) & 1) * 8 + (lane & 7);
    const int bcol = ((lane >> 3) & 1) * 8;
    uint32_t bAddr0 = smem_u32p(&S.B[0][brow][bcol]);

    float acc[4][4][4];
#pragma unroll
    for (int i = 0; i < 4; i++)
#pragma unroll
        for (int j = 0; j < 4; j++)
#pragma unroll
            for (int r = 0; r < 4; r++) acc[i][j][r] = 0.0f;

    ldg(0); sts(0); __syncthreads();

    for (int c = 0; c < NC; c++) {
        const int bi = c & 1;
        const bool more = (c + 1 < NC);
        if (more) ldg(c + 1);

        const uint32_t aB = aAddr0 + bi * TC_BUF_BYTES;
        const uint32_t bB = bAddr0 + bi * TC_BUF_BYTES;
#pragma unroll
        for (int s = 0; s < 2; s++) {
            const uint32_t so = s * 32;
            uint32_t af[4][4];
#pragma unroll
            for (int i = 0; i < 4; i++)
                ldsm4(af[i], aB + i * (16 * 80) + so);
            uint32_t bq[2][4];
#pragma unroll
            for (int jj = 0; jj < 2; jj++)
                ldsm4(bq[jj], bB + jj * (16 * 80) + so);
#pragma unroll
            for (int i = 0; i < 4; i++)
#pragma unroll
                for (int j = 0; j < 4; j++)
                    mma16816(acc[i][j], af[i], bq[j >> 1][(j & 1) * 2], bq[j >> 1][(j & 1) * 2 + 1]);
        }

        if (more) sts(bi ^ 1);
        __syncthreads();
    }

#pragma unroll
    for (int i = 0; i < 4; i++) {
#pragma unroll
        for (int j = 0; j < 4; j++) {
            const int o = o0 + wm * 64 + i * 16 + g;
            const int t = t0 + wn * 32 + j * 8 + 2 * tq;
            const size_t rb = ((size_t)(b * 512 + o)) * 512 + t;
            if (!IS_Y) {
                *(float2*)&g_DU[rb]           = make_float2(acc[i][j][0], acc[i][j][1]);
                *(float2*)&g_DU[rb + 8 * 512] = make_float2(acc[i][j][2], acc[i][j][3]);
            } else {
                float2 d0 = *(const float2*)&g_DU[rb];
                float2 d1 = *(const float2*)&g_DU[rb + 8 * 512];
                *(float2*)&Yout[rb] =
                    make_float2(q8f(acc[i][j][0] + d0.x), q8f(acc[i][j][1] + d0.y));
                *(float2*)&Yout[rb + 8 * 512] =
                    make_float2(q8f(acc[i][j][2] + d1.x), q8f(acc[i][j][3] + d1.y));
            }
        }
    }
}

// ---------------- scan body: fast q8 + distance-2 prefetch ---------------------
__device__ void scan_body(int id) {
    const int n  = id & 511;
    const int bb = id >> 9;
    const float a = g_Aq[n];
    const float* __restrict__ xp = g_X + (size_t)(bb * 512) * 512 + n;
    __nv_bfloat16* __restrict__ sp = g_Sb + (size_t)(bb * 512) * 512 + n;

    float s = 0.0f;
    float bufA[8], bufB[8];
#pragma unroll
    for (int k = 0; k < 8; k++) bufA[k] = xp[k * 512];
#pragma unroll
    for (int k = 0; k < 8; k++) bufB[k] = xp[(8 + k) * 512];

    for (int blk = 0; blk < 64; blk++) {
        float nbuf[8];
        if (blk < 62) {
#pragma unroll
            for (int k = 0; k < 8; k++) nbuf[k] = xp[((blk + 2) * 8 + k) * 512];
        } else {
#pragma unroll
            for (int k = 0; k < 8; k++) nbuf[k] = 0.0f;
        }
#pragma unroll
        for (int k = 0; k < 8; k++) {
            s = q8f(__fadd_rn(__fmul_rn(s, a), bufA[k]));  // unfused, matches ref
            sp[(blk * 8 + k) * 512] = __float2bfloat16(s); // exact
        }
#pragma unroll
        for (int k = 0; k < 8; k++) { bufA[k] = bufB[k]; bufB[k] = nbuf[k]; }
    }
}

// ---------------- fused2: scan (blocks 0-63) + tc<DU> (blocks 64-575) ----------
__global__ __launch_bounds__(256, 2)
void fused2() {
    __shared__ __align__(16) char sm[sizeof(TcSmem)];
    if (blockIdx.x < 64) {
        scan_body(blockIdx.x * 256 + threadIdx.x);
    } else {
        const int id = blockIdx.x - 64;          // 0..511 = 4 x 4 x 32
        tc_body<false>(nullptr, id & 3, (id >> 2) & 3, id >> 4,
                       *reinterpret_cast<TcSmem*>(sm));
    }
}

// ---------------- Y kernel ------------------------------------------------------
__global__ __launch_bounds__(256, 2)
void tc_y(float* __restrict__ Y) {
    __shared__ __align__(16) char sm[sizeof(TcSmem)];
    tc_body<true>(Y, blockIdx.x, blockIdx.y, blockIdx.z,
                  *reinterpret_cast<TcSmem*>(sm));
}

// ---------------- launch --------------------------------------------------------
extern "C" void kernel_launch(void* const* d_in, const int* in_sizes, int n_in,
                              void* d_out, int out_size) {
    const float* u = (const float*)d_in[0];   // (32, 512, 512)  u[b,d,t]
    const float* A = (const float*)d_in[1];
    const float* B = (const float*)d_in[2];
    const float* C = (const float*)d_in[3];
    const float* D = (const float*)d_in[4];
    float* Y = (float*)d_out;                 // (32, 512, 512)  Y[b,o,t]

    quant_weights<<<1024, 256>>>(A, B, C, D);
    fused1<<<1024, 256>>>(u);                 // gemm_x (bit-exact X) || u hi/lo transpose
    fused2<<<576, 256>>>();                   // scan (fast q8) || DU tensor GEMM
    tc_y<<<dim3(4, 4, BZ), 256>>>(Y);         // Y = q8(S @ Cq^T + DU)
}